// round 6
// baseline (speedup 1.0000x reference)
#include <cuda_runtime.h>
#include <math.h>

#define N_NODES 50000
#define N_EDGES 800000
#define IN_DIM  128
#define HID     96
#define OUT_DIM 64
#define MAX_REC 5
#define SCAN_NB ((N_NODES + 1023) / 1024)   // 49

typedef unsigned long long u64;

// ---------------- scratch (no allocations allowed) ----------------
__device__ float g_h[N_NODES * HID];
__device__ float g_agg[N_NODES * HID];
__device__ int   g_steps[N_NODES];
__device__ int   g_deg[N_NODES];
__device__ int   g_rowoff[N_NODES + 1];
__device__ int   g_cursor[N_NODES];
__device__ int   g_col[N_EDGES];
__device__ int   g_hist[8];
__device__ int   g_bcur[8];
__device__ int   g_order[N_NODES];
__device__ int   g_cnt[8];
__device__ int   g_bsum[64];
__device__ int   g_boff[64];
// k-paired weights: g_wp[m][k'][j], m = gate*2 + (0:ih,1:hh); element = (w[j][2k'], w[j][2k'+1])
__device__ float2 g_wp[6 * 48 * HID];
// input weights k-paired: g_win2[k'][j] = (w_in[2k'][j], w_in[2k'+1][j])
__device__ float2 g_win2[64 * HID];

// ---------------- f32x2 helpers ----------------
__device__ __forceinline__ u64 ffma2(u64 a, u64 b, u64 c) {
    u64 d;
    asm("fma.rn.f32x2 %0, %1, %2, %3;" : "=l"(d) : "l"(a), "l"(b), "l"(c));
    return d;
}
__device__ __forceinline__ float2 unpack2(u64 v) {
    float2 r;
    asm("mov.b64 {%0, %1}, %2;" : "=f"(r.x), "=f"(r.y) : "l"(v));
    return r;
}

// ---------------- fused init + weight packing ----------------
__global__ void k_initwt(const float* __restrict__ wih, const float* __restrict__ whh,
                         const float* __restrict__ w_in) {
    int i = blockIdx.x * 256 + threadIdx.x;
    if (i < N_NODES) g_deg[i] = 0;
    if (i < 8) g_hist[i] = 0;
    if (i < 6 * 48 * HID) {
        int m = i / (48 * HID);
        int r = i - m * (48 * HID);
        int kp = r / HID, j = r - kp * HID;
        int gate = m >> 1;
        const float* w = (m & 1) ? whh : wih;
        int base = (gate * HID + j) * HID + 2 * kp;
        g_wp[i] = make_float2(w[base], w[base + 1]);
    }
    if (i < 64 * HID) {
        int kp = i / HID, j = i - kp * HID;
        g_win2[i] = make_float2(w_in[2 * kp * HID + j], w_in[(2 * kp + 1) * HID + j]);
    }
}

// ---------------- degree histogram ----------------
__global__ void k_deg(const int* __restrict__ ei) {
    int e = blockIdx.x * blockDim.x + threadIdx.x;
    if (e < N_EDGES) atomicAdd(&g_deg[ei[e]], 1);
}

// ---------------- multi-block scan ----------------
__global__ __launch_bounds__(1024) void k_scan1() {
    __shared__ int wsum[32];
    __shared__ int woff[32];
    int t = threadIdx.x, lane = t & 31, wid = t >> 5;
    int i = blockIdx.x * 1024 + t;
    int v = (i < N_NODES) ? g_deg[i] : 0;
    int s = v;
#pragma unroll
    for (int o = 1; o < 32; o <<= 1) {
        int u = __shfl_up_sync(0xffffffffu, s, o);
        if (lane >= o) s += u;
    }
    if (lane == 31) wsum[wid] = s;
    __syncthreads();
    if (wid == 0) {
        int ws = wsum[lane];
        int ss = ws;
#pragma unroll
        for (int o = 1; o < 32; o <<= 1) {
            int u = __shfl_up_sync(0xffffffffu, ss, o);
            if (lane >= o) ss += u;
        }
        woff[lane] = ss - ws;
        if (lane == 31) g_bsum[blockIdx.x] = ss;
    }
    __syncthreads();
    if (i < N_NODES) g_rowoff[i] = s - v + woff[wid];
}

// ---------------- fused input GEMM + relu + tau/steps (k-packed) ----------------
// 256 threads, 64 nodes/block. lanes = cols {cj,cj+32,cj+64}; warp = 8 nodes.
// smem: xs[64][130] natural layout + ts[128][16]
__global__ __launch_bounds__(256) void k_input(
    const float* __restrict__ x, const float* __restrict__ b_in,
    const float* __restrict__ tb1, const float* __restrict__ tw2,
    const float* __restrict__ tb2, const float* __restrict__ tw1)
{
    extern __shared__ float sm_in[];
    float* xs = sm_in;                 // [64][130]
    float* ts = xs + 64 * 130;         // [128][16]
    int t = threadIdx.x;
    int node0 = blockIdx.x * 64;

    for (int idx = t; idx < 128 * 16; idx += 256) ts[idx] = tw1[idx];
    for (int idx = t; idx < 64 * 128; idx += 256) {
        int n = idx >> 7, k = idx & 127;
        int gn = node0 + n;
        xs[n * 130 + k] = (gn < N_NODES) ? x[gn * IN_DIM + k] : 0.f;
    }
    __syncthreads();

    int cj = t & 31;      // cols {cj, cj+32, cj+64}
    int ng = t >> 5;      // nodes 8ng..8ng+7
    int nb = 8 * ng;

    u64 acc[3][8];
#pragma unroll
    for (int cc = 0; cc < 3; cc++)
#pragma unroll
        for (int q = 0; q < 8; q++) acc[cc][q] = 0;

    const u64* gw = (const u64*)g_win2;
#pragma unroll 4
    for (int kp = 0; kp < 64; kp++) {
        u64 w2[3];
#pragma unroll
        for (int cc = 0; cc < 3; cc++)
            w2[cc] = __ldg(&gw[kp * HID + cj + 32 * cc]);
        u64 a2[8];
#pragma unroll
        for (int q = 0; q < 8; q++)
            a2[q] = *(const u64*)&xs[(nb + q) * 130 + 2 * kp];
#pragma unroll
        for (int cc = 0; cc < 3; cc++)
#pragma unroll
            for (int q = 0; q < 8; q++)
                acc[cc][q] = ffma2(w2[cc], a2[q], acc[cc][q]);
    }
#pragma unroll
    for (int cc = 0; cc < 3; cc++) {
        int col = cj + 32 * cc;
        float b = b_in[col];
#pragma unroll
        for (int q = 0; q < 8; q++) {
            int gn = node0 + nb + q;
            if (gn < N_NODES) {
                float2 s = unpack2(acc[cc][q]);
                g_h[gn * HID + col] = fmaxf(s.x + s.y + b, 0.f);
            }
        }
    }

    // tau: 4 threads per node
    {
        int tn = t >> 2;
        int tj = t & 3;
        int gn = node0 + tn;
        float hh[4];
#pragma unroll
        for (int u = 0; u < 4; u++) hh[u] = tb1[tj + 4 * u];
#pragma unroll 4
        for (int k = 0; k < 128; k++) {
            float xv = xs[tn * 130 + k];
#pragma unroll
            for (int u = 0; u < 4; u++)
                hh[u] += xv * ts[k * 16 + tj + 4 * u];
        }
        float s = 0.f;
#pragma unroll
        for (int u = 0; u < 4; u++)
            s += fmaxf(hh[u], 0.f) * tw2[tj + 4 * u];
        s += __shfl_xor_sync(0xffffffffu, s, 1);
        s += __shfl_xor_sync(0xffffffffu, s, 2);
        if (tj == 0 && gn < N_NODES) {
            s += tb2[0];
            float sp = fmaxf(s, 0.f) + log1pf(expf(-fabsf(s)));
            float inv = 1.0f / sp;
            int st = (inv >= (float)MAX_REC) ? MAX_REC : (int)inv;
            g_steps[gn] = st;
            atomicAdd(&g_hist[st], 1);
        }
    }
}

__global__ void k_scan2() {
    __shared__ int sh[64];
    int t = threadIdx.x;
    sh[t] = (t < SCAN_NB) ? g_bsum[t] : 0;
    __syncthreads();
    if (t == 0) {
        int run = 0;
        for (int b = 0; b < SCAN_NB; b++) { g_boff[b] = run; run += sh[b]; }
        g_rowoff[N_NODES] = run;
        int suffix = 0;
        int start[6];
        for (int s = 5; s >= 0; s--) { start[s] = suffix; suffix += g_hist[s]; }
        for (int s = 0; s < 6; s++) g_bcur[s] = start[s];
        for (int it = 0; it < 5; it++) g_cnt[it] = start[it];
    }
}

// scan3 + order fused
__global__ __launch_bounds__(1024) void k_scan3() {
    int i = blockIdx.x * 1024 + threadIdx.x;
    if (i < N_NODES) {
        int v = g_rowoff[i] + g_boff[blockIdx.x];
        g_rowoff[i] = v;
        g_cursor[i] = v;
        int s = g_steps[i];
        int pos = atomicAdd(&g_bcur[s], 1);
        g_order[pos] = i;
    }
}

// ---------------- CSR fill ----------------
__global__ void k_csr(const int* __restrict__ ei) {
    int e = blockIdx.x * blockDim.x + threadIdx.x;
    if (e < N_EDGES) {
        int r = ei[e];
        int c = ei[N_EDGES + e];
        int pos = atomicAdd(&g_cursor[r], 1);
        g_col[pos] = c;
    }
}

// ---------------- edge aggregation: warp/node, 8 edges in flight ----------------
__global__ __launch_bounds__(256) void k_agg(int it) {
    int w = blockIdx.x * 8 + (threadIdx.x >> 5);
    if (w >= g_cnt[it]) return;
    int node = g_order[w];
    int lane = threadIdx.x & 31;
    int grp = lane >> 2;
    int l4  = lane & 3;
    int base = g_rowoff[node], end = g_rowoff[node + 1];

    const float4* hi4 = (const float4*)(g_h + node * HID);
    float4 hi[6], acc[6];
#pragma unroll
    for (int u = 0; u < 6; u++) {
        hi[u] = hi4[l4 + 4 * u];
        acc[u] = make_float4(0.f, 0.f, 0.f, 0.f);
    }

    for (int e = base + grp; e < end; e += 8) {
        int cc = __ldg(&g_col[e]);
        const float4* hp = (const float4*)(g_h + cc * HID);
#pragma unroll
        for (int u = 0; u < 6; u++) {
            float4 v = hp[l4 + 4 * u];
            acc[u].x += fabsf(v.x - hi[u].x);
            acc[u].y += fabsf(v.y - hi[u].y);
            acc[u].z += fabsf(v.z - hi[u].z);
            acc[u].w += fabsf(v.w - hi[u].w);
        }
    }
#pragma unroll
    for (int off = 4; off < 32; off <<= 1) {
#pragma unroll
        for (int u = 0; u < 6; u++) {
            acc[u].x += __shfl_xor_sync(0xffffffffu, acc[u].x, off);
            acc[u].y += __shfl_xor_sync(0xffffffffu, acc[u].y, off);
            acc[u].z += __shfl_xor_sync(0xffffffffu, acc[u].z, off);
            acc[u].w += __shfl_xor_sync(0xffffffffu, acc[u].w, off);
        }
    }
    if (grp == 0) {
        float4* ar = (float4*)(g_agg + (long long)node * HID);
#pragma unroll
        for (int u = 0; u < 6; u++) ar[l4 + 4 * u] = acc[u];
    }
}

// ---------------- GRU v4: k-packed f32x2 ----------------
// 64 nodes/tile, 256 threads. lane cj -> cols {cj,cj+32,cj+64}; warp ng -> 8 nodes.
// smem: agg_s[64][96] + h_s[64][96] + wsm (float2, 4 matrices for r/z; reused for n)
__global__ __launch_bounds__(256, 1) void k_gru(
    const float* __restrict__ bih, const float* __restrict__ bhh, int it)
{
    extern __shared__ float sm_g[];
    float* agg_s = sm_g;                     // 64*96
    float* h_s   = agg_s + 64 * 96;          // 64*96
    float2* wsm  = (float2*)(h_s + 64 * 96); // 4*48*96 float2
    int* nodes_s = (int*)(wsm + 4 * 48 * HID);

    int t = threadIdx.x;
    int cnt = g_cnt[it];
    int tile0 = blockIdx.x * 64;
    if (tile0 >= cnt) return;
    int nvalid = min(64, cnt - tile0);

    if (t < 64) nodes_s[t] = g_order[tile0 + min(t, nvalid - 1)];
    __syncthreads();
    // stage acts (natural layout) + 4 r/z weight matrices
    for (int idx = t; idx < 64 * 24; idx += 256) {
        int n = idx / 24, c4 = idx - n * 24;
        int gn = nodes_s[n];
        ((float4*)(agg_s + n * HID))[c4] = ((const float4*)(g_agg + gn * HID))[c4];
        ((float4*)(h_s + n * HID))[c4]   = ((const float4*)(g_h + gn * HID))[c4];
    }
    for (int idx = t; idx < 9216; idx += 256)      // 4*48*96 float2 = 9216 float4
        ((float4*)wsm)[idx] = ((const float4*)g_wp)[idx];
    __syncthreads();

    int cj = t & 31;
    int ng = t >> 5;
    int nb = 8 * ng;

    // ---- fused r + z pass ----
    u64 accR[3][8], accZ[3][8];
#pragma unroll
    for (int cc = 0; cc < 3; cc++)
#pragma unroll
        for (int q = 0; q < 8; q++) { accR[cc][q] = 0; accZ[cc][q] = 0; }

#pragma unroll 2
    for (int kp = 0; kp < 48; kp++) {
        u64 wri[3], wrh[3], wzi[3], wzh[3];
#pragma unroll
        for (int cc = 0; cc < 3; cc++) {
            int j = cj + 32 * cc;
            wri[cc] = *(const u64*)&wsm[(0 * 48 + kp) * HID + j];
            wrh[cc] = *(const u64*)&wsm[(1 * 48 + kp) * HID + j];
            wzi[cc] = *(const u64*)&wsm[(2 * 48 + kp) * HID + j];
            wzh[cc] = *(const u64*)&wsm[(3 * 48 + kp) * HID + j];
        }
#pragma unroll
        for (int q = 0; q < 8; q++) {
            u64 a2 = *(const u64*)&agg_s[(nb + q) * HID + 2 * kp];
            u64 h2 = *(const u64*)&h_s[(nb + q) * HID + 2 * kp];
#pragma unroll
            for (int cc = 0; cc < 3; cc++) {
                accR[cc][q] = ffma2(wri[cc], a2, accR[cc][q]);
                accR[cc][q] = ffma2(wrh[cc], h2, accR[cc][q]);
                accZ[cc][q] = ffma2(wzi[cc], a2, accZ[cc][q]);
                accZ[cc][q] = ffma2(wzh[cc], h2, accZ[cc][q]);
            }
        }
    }
    float r_g[3][8], z_g[3][8];
#pragma unroll
    for (int cc = 0; cc < 3; cc++) {
        int col = cj + 32 * cc;
        float bR = bih[col] + bhh[col];
        float bZ = bih[96 + col] + bhh[96 + col];
#pragma unroll
        for (int q = 0; q < 8; q++) {
            float2 sr = unpack2(accR[cc][q]);
            float2 sz = unpack2(accZ[cc][q]);
            r_g[cc][q] = 1.f / (1.f + expf(-(sr.x + sr.y + bR)));
            z_g[cc][q] = 1.f / (1.f + expf(-(sz.x + sz.y + bZ)));
        }
    }

    // ---- candidate pass ----
    __syncthreads();
    for (int idx = t; idx < 4608; idx += 256)      // 2*48*96 float2 = 4608 float4
        ((float4*)wsm)[idx] = ((const float4*)(g_wp + 4 * 48 * HID))[idx];
    __syncthreads();

    u64 accI[3][8], accH[3][8];
#pragma unroll
    for (int cc = 0; cc < 3; cc++)
#pragma unroll
        for (int q = 0; q < 8; q++) { accI[cc][q] = 0; accH[cc][q] = 0; }

#pragma unroll 2
    for (int kp = 0; kp < 48; kp++) {
        u64 wni[3], wnh[3];
#pragma unroll
        for (int cc = 0; cc < 3; cc++) {
            int j = cj + 32 * cc;
            wni[cc] = *(const u64*)&wsm[(0 * 48 + kp) * HID + j];
            wnh[cc] = *(const u64*)&wsm[(1 * 48 + kp) * HID + j];
        }
#pragma unroll
        for (int q = 0; q < 8; q++) {
            u64 a2 = *(const u64*)&agg_s[(nb + q) * HID + 2 * kp];
            u64 h2 = *(const u64*)&h_s[(nb + q) * HID + 2 * kp];
#pragma unroll
            for (int cc = 0; cc < 3; cc++) {
                accI[cc][q] = ffma2(wni[cc], a2, accI[cc][q]);
                accH[cc][q] = ffma2(wnh[cc], h2, accH[cc][q]);
            }
        }
    }
#pragma unroll
    for (int cc = 0; cc < 3; cc++) {
        int col = cj + 32 * cc;
        float bI = bih[192 + col];
        float bH = bhh[192 + col];
#pragma unroll
        for (int q = 0; q < 8; q++) {
            int n = nb + q;
            float2 si = unpack2(accI[cc][q]);
            float2 sh = unpack2(accH[cc][q]);
            float iv = si.x + si.y + bI;
            float hv = sh.x + sh.y + bH;
            float nv = tanhf(iv + r_g[cc][q] * hv);
            float hold = h_s[n * HID + col];
            float z = z_g[cc][q];
            g_h[nodes_s[n] * HID + col] = (1.f - z) * nv + z * hold;
        }
    }
}

// ---------------- output GEMM ----------------
__global__ __launch_bounds__(256) void k_out(
    const float* __restrict__ wo, const float* __restrict__ bo,
    float* __restrict__ out)
{
    __shared__ float ws[96 * 64];
    __shared__ float hs[32 * 97];
    int t = threadIdx.x;
    int node0 = blockIdx.x * 32;
    for (int idx = t; idx < 96 * 64; idx += 256) ws[idx] = wo[idx];
    for (int idx = t; idx < 32 * 96; idx += 256) {
        int n = idx / 96, k = idx - n * 96;
        int gn = node0 + n;
        hs[n * 97 + k] = (gn < N_NODES) ? g_h[gn * HID + k] : 0.f;
    }
    __syncthreads();
    int j = t & 63, nt = t >> 6;
    float acc[8];
#pragma unroll
    for (int nn = 0; nn < 8; nn++) acc[nn] = bo[j];
    for (int k = 0; k < 96; k++) {
        float w = ws[k * 64 + j];
#pragma unroll
        for (int nn = 0; nn < 8; nn++)
            acc[nn] += hs[(nt + 4 * nn) * 97 + k] * w;
    }
#pragma unroll
    for (int nn = 0; nn < 8; nn++) {
        int gn = node0 + nt + 4 * nn;
        if (gn < N_NODES) out[gn * OUT_DIM + j] = acc[nn];
    }
}

// ---------------- launch ----------------
extern "C" void kernel_launch(void* const* d_in, const int* in_sizes, int n_in,
                              void* d_out, int out_size)
{
    const float* x    = (const float*)d_in[0];
    const int*   ei   = (const int*)d_in[1];
    const float* w_in = (const float*)d_in[2];
    const float* b_in = (const float*)d_in[3];
    const float* tw1  = (const float*)d_in[4];
    const float* tb1  = (const float*)d_in[5];
    const float* tw2  = (const float*)d_in[6];
    const float* tb2  = (const float*)d_in[7];
    const float* wih  = (const float*)d_in[8];
    const float* whh  = (const float*)d_in[9];
    const float* bih  = (const float*)d_in[10];
    const float* bhh  = (const float*)d_in[11];
    const float* wo   = (const float*)d_in[12];
    const float* bo   = (const float*)d_in[13];
    float* out = (float*)d_out;

    const int smem_in  = (64 * 130 + 128 * 16) * 4;                      // 41472 B
    const int smem_gru = (64 * 96 * 2) * 4 + 4 * 48 * 96 * 8 + 64 * 4;   // 196864 B
    cudaFuncSetAttribute(k_input, cudaFuncAttributeMaxDynamicSharedMemorySize, smem_in);
    cudaFuncSetAttribute(k_gru,   cudaFuncAttributeMaxDynamicSharedMemorySize, smem_gru);

    k_initwt<<<(N_NODES + 255) / 256, 256>>>(wih, whh, w_in);            // 1
    k_deg<<<(N_EDGES + 255) / 256, 256>>>(ei);                           // 2
    k_scan1<<<SCAN_NB, 1024>>>();                                        // 3
    k_input<<<(N_NODES + 63) / 64, 256, smem_in>>>(x, b_in,              // 4 (profiled)
                                                   tb1, tw2, tb2, tw1);
    k_scan2<<<1, 64>>>();                                                // 5
    k_scan3<<<SCAN_NB, 1024>>>();                                        // 6 (+order)
    k_csr<<<(N_EDGES + 255) / 256, 256>>>(ei);                           // 7

    for (int it = 0; it < MAX_REC; it++) {
        k_agg<<<(N_NODES + 7) / 8, 256>>>(it);
        k_gru<<<(N_NODES + 63) / 64, 256, smem_gru>>>(bih, bhh, it);
    }
    k_out<<<(N_NODES + 31) / 32, 256>>>(wo, bo, out);
}

// round 7
// speedup vs baseline: 1.1762x; 1.1762x over previous
#include <cuda_runtime.h>
#include <math.h>

#define N_NODES 50000
#define N_EDGES 800000
#define IN_DIM  128
#define HID     96
#define OUT_DIM 64
#define MAX_REC 5
#define SCAN_NB ((N_NODES + 1023) / 1024)   // 49

typedef unsigned long long u64;

// ---------------- scratch (no allocations allowed) ----------------
__device__ float g_h[N_NODES * HID];
__device__ float g_agg[N_NODES * HID];
__device__ int   g_steps[N_NODES];
__device__ int   g_deg[N_NODES];
__device__ int   g_rowoff[N_NODES + 1];
__device__ int   g_cursor[N_NODES];
__device__ int   g_col[N_EDGES];
__device__ int   g_hist[8];
__device__ int   g_bcur[8];
__device__ int   g_order[N_NODES];
__device__ int   g_cnt[8];
__device__ int   g_bsum[64];
__device__ int   g_boff[64];
__device__ float g_wt_ih[3 * HID * HID];   // [chunk][k][j]
__device__ float g_wt_hh[3 * HID * HID];

// ---------------- f32x2 helpers ----------------
__device__ __forceinline__ u64 ffma2(u64 a, u64 b, u64 c) {
    u64 d;
    asm("fma.rn.f32x2 %0, %1, %2, %3;" : "=l"(d) : "l"(a), "l"(b), "l"(c));
    return d;
}
__device__ __forceinline__ u64 pack2(float x, float y) {
    u64 r;
    asm("mov.b64 %0, {%1, %2};" : "=l"(r) : "f"(x), "f"(y));
    return r;
}
__device__ __forceinline__ float2 unpack2(u64 v) {
    float2 r;
    asm("mov.b64 {%0, %1}, %2;" : "=f"(r.x), "=f"(r.y) : "l"(v));
    return r;
}
__device__ __forceinline__ float fast_sigmoid(float x) {
    return __fdividef(1.f, 1.f + __expf(-x));
}
__device__ __forceinline__ float fast_tanh(float x) {
    return 1.f - __fdividef(2.f, __expf(2.f * x) + 1.f);
}

// ---------------- fused init + weight transpose ----------------
__global__ void k_initwt(const float* __restrict__ wih, const float* __restrict__ whh) {
    int i = blockIdx.x * 256 + threadIdx.x;
    if (i < N_NODES) g_deg[i] = 0;
    if (i < 8) g_hist[i] = 0;
    if (i < 3 * HID * HID) {
        int chunk = i / (HID * HID);
        int r = i - chunk * HID * HID;
        int k = r / HID, j = r - k * HID;
        g_wt_ih[i] = wih[(chunk * HID + j) * HID + k];
        g_wt_hh[i] = whh[(chunk * HID + j) * HID + k];
    }
}

// ---------------- degree histogram ----------------
__global__ void k_deg(const int* __restrict__ ei) {
    int e = blockIdx.x * blockDim.x + threadIdx.x;
    if (e < N_EDGES) atomicAdd(&g_deg[ei[e]], 1);
}

// ---------------- multi-block scan ----------------
__global__ __launch_bounds__(1024) void k_scan1() {
    __shared__ int wsum[32];
    __shared__ int woff[32];
    int t = threadIdx.x, lane = t & 31, wid = t >> 5;
    int i = blockIdx.x * 1024 + t;
    int v = (i < N_NODES) ? g_deg[i] : 0;
    int s = v;
#pragma unroll
    for (int o = 1; o < 32; o <<= 1) {
        int u = __shfl_up_sync(0xffffffffu, s, o);
        if (lane >= o) s += u;
    }
    if (lane == 31) wsum[wid] = s;
    __syncthreads();
    if (wid == 0) {
        int ws = wsum[lane];
        int ss = ws;
#pragma unroll
        for (int o = 1; o < 32; o <<= 1) {
            int u = __shfl_up_sync(0xffffffffu, ss, o);
            if (lane >= o) ss += u;
        }
        woff[lane] = ss - ws;
        if (lane == 31) g_bsum[blockIdx.x] = ss;
    }
    __syncthreads();
    if (i < N_NODES) g_rowoff[i] = s - v + woff[wid];
}

// ---------------- fused input GEMM + relu + tau/steps ----------------
__global__ __launch_bounds__(256) void k_input(
    const float* __restrict__ x, const float* __restrict__ w_in,
    const float* __restrict__ b_in, const float* __restrict__ tw1,
    const float* __restrict__ tb1, const float* __restrict__ tw2,
    const float* __restrict__ tb2)
{
    extern __shared__ float sm_in[];
    float* xs_t = sm_in;               // [128][66]
    float* ts   = xs_t + 128 * 66;     // [128][16]
    int t = threadIdx.x;
    int node0 = blockIdx.x * 64;

#pragma unroll
    for (int idx = t; idx < 128 * 16; idx += 256) ts[idx] = tw1[idx];
#pragma unroll
    for (int idx = t; idx < 64 * 128; idx += 256) {
        int n = idx >> 7, k = idx & 127;
        int gn = node0 + n;
        xs_t[k * 66 + n] = (gn < N_NODES) ? x[gn * IN_DIM + k] : 0.f;
    }
    __syncthreads();

    int cj = t & 31;     // cols {cj, cj+32, cj+64}
    int pg = t >> 5;     // node pairs {pg, pg+8, pg+16, pg+24}

    u64 acc[3][4];
#pragma unroll
    for (int cc = 0; cc < 3; cc++) {
        float b = b_in[cj + 32 * cc];
        u64 bp = pack2(b, b);
#pragma unroll
        for (int q = 0; q < 4; q++) acc[cc][q] = bp;
    }
#pragma unroll 8
    for (int k = 0; k < 128; k++) {
        u64 wd[3];
#pragma unroll
        for (int cc = 0; cc < 3; cc++) {
            float w = __ldg(&w_in[k * 96 + cj + 32 * cc]);
            wd[cc] = pack2(w, w);
        }
        u64 ap[4];
#pragma unroll
        for (int q = 0; q < 4; q++)
            ap[q] = *(const u64*)&xs_t[k * 66 + 2 * (pg + 8 * q)];
#pragma unroll
        for (int cc = 0; cc < 3; cc++)
#pragma unroll
            for (int q = 0; q < 4; q++)
                acc[cc][q] = ffma2(wd[cc], ap[q], acc[cc][q]);
    }
#pragma unroll
    for (int cc = 0; cc < 3; cc++) {
        int col = cj + 32 * cc;
#pragma unroll
        for (int q = 0; q < 4; q++) {
            int n0 = node0 + 2 * (pg + 8 * q);
            float2 g = unpack2(acc[cc][q]);
            if (n0 < N_NODES)     g_h[n0 * HID + col]       = fmaxf(g.x, 0.f);
            if (n0 + 1 < N_NODES) g_h[(n0 + 1) * HID + col] = fmaxf(g.y, 0.f);
        }
    }

    // tau: 4 threads per node
    {
        int tn = t >> 2;
        int tj = t & 3;
        int gn = node0 + tn;
        float hh[4];
#pragma unroll
        for (int u = 0; u < 4; u++) hh[u] = tb1[tj + 4 * u];
#pragma unroll 4
        for (int k = 0; k < 128; k++) {
            float xv = xs_t[k * 66 + tn];
#pragma unroll
            for (int u = 0; u < 4; u++)
                hh[u] += xv * ts[k * 16 + tj + 4 * u];
        }
        float s = 0.f;
#pragma unroll
        for (int u = 0; u < 4; u++)
            s += fmaxf(hh[u], 0.f) * tw2[tj + 4 * u];
        s += __shfl_xor_sync(0xffffffffu, s, 1);
        s += __shfl_xor_sync(0xffffffffu, s, 2);
        if (tj == 0 && gn < N_NODES) {
            s += tb2[0];
            // exact softplus (keep libm here; runs once per node)
            float sp = fmaxf(s, 0.f) + log1pf(expf(-fabsf(s)));
            float inv = 1.0f / sp;
            int st = (inv >= (float)MAX_REC) ? MAX_REC : (int)inv;
            g_steps[gn] = st;
            atomicAdd(&g_hist[st], 1);
        }
    }
}

__global__ void k_scan2() {
    __shared__ int sh[64];
    int t = threadIdx.x;
    sh[t] = (t < SCAN_NB) ? g_bsum[t] : 0;
    __syncthreads();
    if (t == 0) {
        int run = 0;
        for (int b = 0; b < SCAN_NB; b++) { g_boff[b] = run; run += sh[b]; }
        g_rowoff[N_NODES] = run;
        int suffix = 0;
        int start[6];
        for (int s = 5; s >= 0; s--) { start[s] = suffix; suffix += g_hist[s]; }
        for (int s = 0; s < 6; s++) g_bcur[s] = start[s];
        for (int it = 0; it < 5; it++) g_cnt[it] = start[it];
    }
}

// scan3 + order fused
__global__ __launch_bounds__(1024) void k_scan3() {
    int i = blockIdx.x * 1024 + threadIdx.x;
    if (i < N_NODES) {
        int v = g_rowoff[i] + g_boff[blockIdx.x];
        g_rowoff[i] = v;
        g_cursor[i] = v;
        int s = g_steps[i];
        int pos = atomicAdd(&g_bcur[s], 1);
        g_order[pos] = i;
    }
}

// ---------------- CSR fill ----------------
__global__ void k_csr(const int* __restrict__ ei) {
    int e = blockIdx.x * blockDim.x + threadIdx.x;
    if (e < N_EDGES) {
        int r = ei[e];
        int c = ei[N_EDGES + e];
        int pos = atomicAdd(&g_cursor[r], 1);
        g_col[pos] = c;
    }
}

// ---------------- edge aggregation: warp/node, 8 edges in flight ----------------
__global__ __launch_bounds__(256) void k_agg(int it) {
    int w = blockIdx.x * 8 + (threadIdx.x >> 5);
    if (w >= g_cnt[it]) return;
    int node = g_order[w];
    int lane = threadIdx.x & 31;
    int grp = lane >> 2;
    int l4  = lane & 3;
    int base = g_rowoff[node], end = g_rowoff[node + 1];

    const float4* hi4 = (const float4*)(g_h + node * HID);
    float4 hi[6], acc[6];
#pragma unroll
    for (int u = 0; u < 6; u++) {
        hi[u] = hi4[l4 + 4 * u];
        acc[u] = make_float4(0.f, 0.f, 0.f, 0.f);
    }

#pragma unroll 2
    for (int e = base + grp; e < end; e += 8) {
        int cc = __ldg(&g_col[e]);
        const float4* hp = (const float4*)(g_h + cc * HID);
#pragma unroll
        for (int u = 0; u < 6; u++) {
            float4 v = hp[l4 + 4 * u];
            acc[u].x += fabsf(v.x - hi[u].x);
            acc[u].y += fabsf(v.y - hi[u].y);
            acc[u].z += fabsf(v.z - hi[u].z);
            acc[u].w += fabsf(v.w - hi[u].w);
        }
    }
#pragma unroll
    for (int off = 4; off < 32; off <<= 1) {
#pragma unroll
        for (int u = 0; u < 6; u++) {
            acc[u].x += __shfl_xor_sync(0xffffffffu, acc[u].x, off);
            acc[u].y += __shfl_xor_sync(0xffffffffu, acc[u].y, off);
            acc[u].z += __shfl_xor_sync(0xffffffffu, acc[u].z, off);
            acc[u].w += __shfl_xor_sync(0xffffffffu, acc[u].w, off);
        }
    }
    if (grp == 0) {
        float4* ar = (float4*)(g_agg + (long long)node * HID);
#pragma unroll
        for (int u = 0; u < 6; u++) ar[l4 + 4 * u] = acc[u];
    }
}

// ---------------- GRU v3 (proven) + unrolled staging + fast activations ------
// 64 nodes/tile, 256 threads. cp = t&15 -> col-pairs {cp, cp+16, cp+32};
// ng = t>>4 -> nodes {4ng..4ng+3}.
__global__ __launch_bounds__(256, 1) void k_gru(
    const float* __restrict__ bih, const float* __restrict__ bhh, int it)
{
    extern __shared__ float sm_g[];
    float* agg_s = sm_g;                 // 6400
    float* h_s   = agg_s + 6400;         // 6400
    float* w0a   = h_s + 6400;           // 9216 (r: ih)
    float* w0b   = w0a + 9216;           // 9216 (r: hh)
    float* w1a   = w0b + 9216;           // 9216 (z: ih)
    float* w1b   = w1a + 9216;           // 9216 (z: hh)
    int* nodes_s = (int*)(w1b + 9216);

    int t = threadIdx.x;
    int cnt = g_cnt[it];
    int tile0 = blockIdx.x * 64;
    if (tile0 >= cnt) return;
    int nvalid = min(64, cnt - tile0);

    if (t < 64) nodes_s[t] = g_order[tile0 + min(t, nvalid - 1)];
    __syncthreads();
    // stage acts (coalesced) + 4 r/z weight matrices — fully unrolled for MLP
#pragma unroll
    for (int idx = t; idx < 64 * 24; idx += 256) {
        int n = idx / 24, c4 = idx - n * 24;
        int gn = nodes_s[n];
        ((float4*)(agg_s + n * 100))[c4] = ((const float4*)(g_agg + gn * HID))[c4];
        ((float4*)(h_s + n * 100))[c4]   = ((const float4*)(g_h + gn * HID))[c4];
    }
#pragma unroll
    for (int idx = t; idx < 2304; idx += 256) {
        ((float4*)w0a)[idx] = ((const float4*)g_wt_ih)[idx];
        ((float4*)w0b)[idx] = ((const float4*)g_wt_hh)[idx];
        ((float4*)w1a)[idx] = ((const float4*)(g_wt_ih + 9216))[idx];
        ((float4*)w1b)[idx] = ((const float4*)(g_wt_hh + 9216))[idx];
    }
    __syncthreads();

    int cp = t & 15;     // col-pairs {cp, cp+16, cp+32} (cols 2p, 2p+1)
    int ng = t >> 4;     // nodes 4ng..4ng+3
    int nb = 4 * ng;

    u64 accR[3][4], accZ[3][4];
#pragma unroll
    for (int cc = 0; cc < 3; cc++) {
        int c2 = 2 * (cp + 16 * cc);
        float2 bi0 = *(const float2*)&bih[c2];
        float2 bh0 = *(const float2*)&bhh[c2];
        float2 bi1 = *(const float2*)&bih[96 + c2];
        float2 bh1 = *(const float2*)&bhh[96 + c2];
        u64 bR = pack2(bi0.x + bh0.x, bi0.y + bh0.y);
        u64 bZ = pack2(bi1.x + bh1.x, bi1.y + bh1.y);
#pragma unroll
        for (int q = 0; q < 4; q++) { accR[cc][q] = bR; accZ[cc][q] = bZ; }
    }
#pragma unroll 4
    for (int k = 0; k < 96; k++) {
        u64 wra[3], wrb[3], wza[3], wzb[3];
#pragma unroll
        for (int cc = 0; cc < 3; cc++) {
            int o = k * 96 + 2 * (cp + 16 * cc);
            wra[cc] = *(const u64*)&w0a[o];
            wrb[cc] = *(const u64*)&w0b[o];
            wza[cc] = *(const u64*)&w1a[o];
            wzb[cc] = *(const u64*)&w1b[o];
        }
        u64 a2[4], h2[4];
#pragma unroll
        for (int q = 0; q < 4; q++) {
            float a  = agg_s[(nb + q) * 100 + k];
            float hv = h_s[(nb + q) * 100 + k];
            a2[q] = pack2(a, a);
            h2[q] = pack2(hv, hv);
        }
#pragma unroll
        for (int cc = 0; cc < 3; cc++)
#pragma unroll
            for (int q = 0; q < 4; q++) {
                accR[cc][q] = ffma2(wra[cc], a2[q], accR[cc][q]);
                accR[cc][q] = ffma2(wrb[cc], h2[q], accR[cc][q]);
                accZ[cc][q] = ffma2(wza[cc], a2[q], accZ[cc][q]);
                accZ[cc][q] = ffma2(wzb[cc], h2[q], accZ[cc][q]);
            }
    }
    u64 r_g[3][4], z_g[3][4];
#pragma unroll
    for (int cc = 0; cc < 3; cc++)
#pragma unroll
        for (int q = 0; q < 4; q++) {
            float2 gr = unpack2(accR[cc][q]);
            float2 gz = unpack2(accZ[cc][q]);
            r_g[cc][q] = pack2(fast_sigmoid(gr.x), fast_sigmoid(gr.y));
            z_g[cc][q] = pack2(fast_sigmoid(gz.x), fast_sigmoid(gz.y));
        }

    // chunk 2: candidate gate
    __syncthreads();
#pragma unroll
    for (int idx = t; idx < 2304; idx += 256) {
        ((float4*)w0a)[idx] = ((const float4*)(g_wt_ih + 18432))[idx];
        ((float4*)w0b)[idx] = ((const float4*)(g_wt_hh + 18432))[idx];
    }
    __syncthreads();

    u64 ai[3][4], ah[3][4];
#pragma unroll
    for (int cc = 0; cc < 3; cc++) {
        int c2 = 2 * (cp + 16 * cc);
        float2 b1 = *(const float2*)&bih[192 + c2];
        float2 b2 = *(const float2*)&bhh[192 + c2];
        u64 p1 = pack2(b1.x, b1.y), p2 = pack2(b2.x, b2.y);
#pragma unroll
        for (int q = 0; q < 4; q++) { ai[cc][q] = p1; ah[cc][q] = p2; }
    }
#pragma unroll 4
    for (int k = 0; k < 96; k++) {
        u64 wa[3], wb[3];
#pragma unroll
        for (int cc = 0; cc < 3; cc++) {
            int o = k * 96 + 2 * (cp + 16 * cc);
            wa[cc] = *(const u64*)&w0a[o];
            wb[cc] = *(const u64*)&w0b[o];
        }
        u64 a2[4], h2[4];
#pragma unroll
        for (int q = 0; q < 4; q++) {
            float a  = agg_s[(nb + q) * 100 + k];
            float hv = h_s[(nb + q) * 100 + k];
            a2[q] = pack2(a, a);
            h2[q] = pack2(hv, hv);
        }
#pragma unroll
        for (int cc = 0; cc < 3; cc++)
#pragma unroll
            for (int q = 0; q < 4; q++) {
                ai[cc][q] = ffma2(wa[cc], a2[q], ai[cc][q]);
                ah[cc][q] = ffma2(wb[cc], h2[q], ah[cc][q]);
            }
    }
#pragma unroll
    for (int cc = 0; cc < 3; cc++) {
        int c2 = 2 * (cp + 16 * cc);
#pragma unroll
        for (int q = 0; q < 4; q++) {
            int n = nb + q;
            float2 vi = unpack2(ai[cc][q]);
            float2 vh = unpack2(ah[cc][q]);
            float2 rr = unpack2(r_g[cc][q]);
            float2 zz = unpack2(z_g[cc][q]);
            float hold0 = h_s[n * 100 + c2];
            float hold1 = h_s[n * 100 + c2 + 1];
            float nv0 = fast_tanh(vi.x + rr.x * vh.x);
            float nv1 = fast_tanh(vi.y + rr.y * vh.y);
            float h0 = (1.f - zz.x) * nv0 + zz.x * hold0;
            float h1 = (1.f - zz.y) * nv1 + zz.y * hold1;
            *(float2*)&g_h[nodes_s[n] * HID + c2] = make_float2(h0, h1);
        }
    }
}

// ---------------- output GEMM ----------------
__global__ __launch_bounds__(256) void k_out(
    const float* __restrict__ wo, const float* __restrict__ bo,
    float* __restrict__ out)
{
    __shared__ float ws[96 * 64];
    __shared__ float hs[32 * 97];
    int t = threadIdx.x;
    int node0 = blockIdx.x * 32;
#pragma unroll
    for (int idx = t; idx < 96 * 64; idx += 256) ws[idx] = wo[idx];
#pragma unroll
    for (int idx = t; idx < 32 * 96; idx += 256) {
        int n = idx / 96, k = idx - n * 96;
        int gn = node0 + n;
        hs[n * 97 + k] = (gn < N_NODES) ? g_h[gn * HID + k] : 0.f;
    }
    __syncthreads();
    int j = t & 63, nt = t >> 6;
    float acc[8];
#pragma unroll
    for (int nn = 0; nn < 8; nn++) acc[nn] = bo[j];
#pragma unroll 4
    for (int k = 0; k < 96; k++) {
        float w = ws[k * 64 + j];
#pragma unroll
        for (int nn = 0; nn < 8; nn++)
            acc[nn] += hs[(nt + 4 * nn) * 97 + k] * w;
    }
#pragma unroll
    for (int nn = 0; nn < 8; nn++) {
        int gn = node0 + nt + 4 * nn;
        if (gn < N_NODES) out[gn * OUT_DIM + j] = acc[nn];
    }
}

// ---------------- launch ----------------
extern "C" void kernel_launch(void* const* d_in, const int* in_sizes, int n_in,
                              void* d_out, int out_size)
{
    const float* x    = (const float*)d_in[0];
    const int*   ei   = (const int*)d_in[1];
    const float* w_in = (const float*)d_in[2];
    const float* b_in = (const float*)d_in[3];
    const float* tw1  = (const float*)d_in[4];
    const float* tb1  = (const float*)d_in[5];
    const float* tw2  = (const float*)d_in[6];
    const float* tb2  = (const float*)d_in[7];
    const float* wih  = (const float*)d_in[8];
    const float* whh  = (const float*)d_in[9];
    const float* bih  = (const float*)d_in[10];
    const float* bhh  = (const float*)d_in[11];
    const float* wo   = (const float*)d_in[12];
    const float* bo   = (const float*)d_in[13];
    float* out = (float*)d_out;

    const int smem_in  = (128 * 66 + 128 * 16) * 4;                     // 41984 B
    const int smem_gru = (6400 * 2 + 9216 * 4) * 4 + 64 * 4;            // 198912 B
    cudaFuncSetAttribute(k_input, cudaFuncAttributeMaxDynamicSharedMemorySize, smem_in);
    cudaFuncSetAttribute(k_gru,   cudaFuncAttributeMaxDynamicSharedMemorySize, smem_gru);

    k_initwt<<<(N_NODES + 255) / 256, 256>>>(wih, whh);               // 1
    k_deg<<<(N_EDGES + 255) / 256, 256>>>(ei);                        // 2
    k_scan1<<<SCAN_NB, 1024>>>();                                     // 3
    k_input<<<(N_NODES + 63) / 64, 256, smem_in>>>(x, w_in, b_in,     // 4 (profiled)
                                                   tw1, tb1, tw2, tb2);
    k_scan2<<<1, 64>>>();                                             // 5
    k_scan3<<<SCAN_NB, 1024>>>();                                     // 6 (+order)
    k_csr<<<(N_EDGES + 255) / 256, 256>>>(ei);                        // 7

    for (int it = 0; it < MAX_REC; it++) {
        k_agg<<<(N_NODES + 7) / 8, 256>>>(it);
        k_gru<<<(N_NODES + 63) / 64, 256, smem_gru>>>(bih, bhh, it);
    }
    k_out<<<(N_NODES + 31) / 32, 256>>>(wo, bo, out);
}